// round 3
// baseline (speedup 1.0000x reference)
#include <cuda_runtime.h>
#include <math.h>

// Problem constants
#define BB 4
#define TT 2048
#define CC 2048
#define HH 16
#define DD 128
#define N3 6144   // 3*C
#define MM 8192   // B*T

// Scratch (device globals; no allocation allowed)
__device__ float g_q[BB*HH*TT*DD];     // [B,H,T,D]
__device__ float g_k[BB*HH*TT*DD];
__device__ float g_v[BB*HH*TT*DD];
__device__ float g_att[BB*TT*CC];      // [B,T,C]
__device__ float g_cos[TT*64];         // RoPE cos table [t][j], j<64
__device__ float g_sin[TT*64];         // RoPE sin table

// ---------------------------------------------------------------------------
// RoPE table: inv_freq in fp64 (matches fp32 reference), angles via sincosf
// (same math as reference's cos/sin of t*inv_freq in fp32).
// ---------------------------------------------------------------------------
__global__ void rope_table_kernel() {
    int t = blockIdx.x;
    int j = threadIdx.x;            // 0..63
    float inv = (float)(1.0 / pow(10000.0, (2.0 * j) / 128.0));
    float s, c;
    sincosf((float)t * inv, &s, &c);
    g_cos[t * 64 + j] = c;
    g_sin[t * 64 + j] = s;
}

#define AS_STRIDE 132

// ---------------------------------------------------------------------------
// QKV GEMM + fused RoPE: qkv[m,n] = sum_k x[m,k] * w_qkv[k,n]
// 128x128x8 double-buffered tile, 256 threads, 8x8 micro-tile.
// Epilogue applies RoPE (q,k only) via lane^8 shuffle, scatters to [B,H,T,D].
// ---------------------------------------------------------------------------
__global__ __launch_bounds__(256, 2) void qkv_gemm_kernel(const float* __restrict__ X,
                                                          const float* __restrict__ W) {
    __shared__ float As[2][8][AS_STRIDE];   // transposed: As[buf][k][m]
    __shared__ float Bs[2][8][128];         // natural:    Bs[buf][k][n]

    const int bx = blockIdx.x;     // N tile: 0..47
    const int by = blockIdx.y;     // M tile: 0..63
    const int tid = threadIdx.x;
    const int tx = tid & 15, ty = tid >> 4;

    float acc[8][8];
#pragma unroll
    for (int i = 0; i < 8; i++)
#pragma unroll
        for (int j = 0; j < 8; j++) acc[i][j] = 0.f;

    const int ar = tid >> 1, ac = (tid & 1) * 4;       // A: 128 rows x 8 cols
    const int br = tid >> 5, bc = (tid & 31) * 4;      // B: 8 rows x 128 cols

    const float* Aptr = X + (size_t)(by * 128 + ar) * 2048 + ac;
    const float* Bptr = W + (size_t)br * N3 + bx * 128 + bc;

    // Preload tile 0
    float4 av = *(const float4*)(Aptr);
    float4 bv = *(const float4*)(Bptr);
    As[0][ac + 0][ar] = av.x; As[0][ac + 1][ar] = av.y;
    As[0][ac + 2][ar] = av.z; As[0][ac + 3][ar] = av.w;
    *(float4*)&Bs[0][br][bc] = bv;
    __syncthreads();

    for (int k0 = 0; k0 < 2048; k0 += 8) {
        const int buf = (k0 >> 3) & 1;
        const int nxt = buf ^ 1;
        const bool more = (k0 + 8) < 2048;
        if (more) {
            av = *(const float4*)(Aptr + k0 + 8);
            bv = *(const float4*)(Bptr + (size_t)(k0 + 8) * N3);
        }
#pragma unroll
        for (int kk = 0; kk < 8; kk++) {
            float a[8], b[8];
            *(float4*)(a)     = *(const float4*)&As[buf][kk][ty * 8];
            *(float4*)(a + 4) = *(const float4*)&As[buf][kk][ty * 8 + 4];
            *(float4*)(b)     = *(const float4*)&Bs[buf][kk][tx * 8];
            *(float4*)(b + 4) = *(const float4*)&Bs[buf][kk][tx * 8 + 4];
#pragma unroll
            for (int i = 0; i < 8; i++)
#pragma unroll
                for (int j = 0; j < 8; j++) acc[i][j] += a[i] * b[j];
        }
        if (more) {
            As[nxt][ac + 0][ar] = av.x; As[nxt][ac + 1][ar] = av.y;
            As[nxt][ac + 2][ar] = av.z; As[nxt][ac + 3][ar] = av.w;
            *(float4*)&Bs[nxt][br][bc] = bv;
        }
        __syncthreads();
    }

    // Epilogue
    const int n0 = bx * 128;
    const int which = n0 >> 11;          // 0=q,1=k,2=v
    const int h = (n0 & 2047) >> 7;      // head (constant per block)
    const int b_ = by >> 4;
    const int t0 = (by & 15) * 128;

    // Fused RoPE for q,k tiles. Thread columns d = tx*8+j lie in one half;
    // the partner element (d +- 64) is in lane tid^8 (same warp). The shuffle
    // exchanges pre-update values in lockstep, so in-place rotation is safe.
    if (which < 2) {
        const bool hi = (tx >= 8);
        const int jb = (tx & 7) * 8;
#pragma unroll
        for (int i = 0; i < 8; i++) {
            const int t = t0 + ty * 8 + i;
            const float* cb = g_cos + t * 64 + jb;
            const float* sb = g_sin + t * 64 + jb;
            float c[8], s[8];
            *(float4*)(c)     = *(const float4*)(cb);
            *(float4*)(c + 4) = *(const float4*)(cb + 4);
            *(float4*)(s)     = *(const float4*)(sb);
            *(float4*)(s + 4) = *(const float4*)(sb + 4);
#pragma unroll
            for (int j = 0; j < 8; j++) {
                float part = __shfl_xor_sync(0xffffffffu, acc[i][j], 8);
                acc[i][j] = hi ? fmaf(part, s[j], acc[i][j] * c[j])
                               : fmaf(-part, s[j], acc[i][j] * c[j]);
            }
        }
    }

    float* base = (which == 0) ? g_q : ((which == 1) ? g_k : g_v);
    float* out = base + (size_t)(b_ * HH + h) * TT * DD;
#pragma unroll
    for (int i = 0; i < 8; i++) {
        int t = t0 + ty * 8 + i;
        float* o = out + (size_t)t * DD + tx * 8;
        *(float4*)(o)     = make_float4(acc[i][0], acc[i][1], acc[i][2], acc[i][3]);
        *(float4*)(o + 4) = make_float4(acc[i][4], acc[i][5], acc[i][6], acc[i][7]);
    }
}

// ---------------------------------------------------------------------------
// Causal flash attention (fp32). Br=Bc=64, 256 threads.
// Grid: (T/64, B*H). K stored transposed with stride 65 (conflict-free reads).
// Qs padded to stride 132 -> conflict-free phase-1 row reads.
// ---------------------------------------------------------------------------
#define QS_STRIDE 132
#define ATTN_SMEM_FLOATS (64*QS_STRIDE + 128*65 + 64*128 + 64*65 + 192)
#define ATTN_SMEM_BYTES  (ATTN_SMEM_FLOATS * 4)

__global__ __launch_bounds__(256) void attn_kernel() {
    extern __shared__ float sm[];
    float* Qs  = sm;                   // [64][132]
    float* Kst = Qs + 64 * QS_STRIDE;  // [128][65]  K transposed
    float* Vs  = Kst + 128 * 65;       // [64][128]
    float* Ps  = Vs + 64 * 128;        // [64][65]
    float* m_s  = Ps + 64 * 65;        // [64]
    float* l_s  = m_s + 64;            // [64]
    float* al_s = l_s + 64;            // [64]

    const int tid = threadIdx.x;
    const int tx = tid & 15, ty = tid >> 4;
    const int bh = blockIdx.y;
    const int qt = blockIdx.x;
    const int q0 = qt * 64;
    const float scale = 0.08838834764831845f;   // 1/sqrt(128)

    const float* qg = g_q + (size_t)bh * TT * DD;
    const float* kg = g_k + (size_t)bh * TT * DD;
    const float* vg = g_v + (size_t)bh * TT * DD;

    // Load Q tile (64x128): 2048 float4 / 256 threads = 8 each
#pragma unroll
    for (int it = 0; it < 8; it++) {
        int lin = tid + it * 256;
        int r = lin >> 5;
        int c4 = (lin & 31) * 4;
        *(float4*)&Qs[r * QS_STRIDE + c4] = *(const float4*)(qg + (size_t)(q0 + r) * 128 + c4);
    }
    if (tid < 64) { m_s[tid] = -INFINITY; l_s[tid] = 0.f; }

    float acc[4][8];
#pragma unroll
    for (int i = 0; i < 4; i++)
#pragma unroll
        for (int c = 0; c < 8; c++) acc[i][c] = 0.f;

    for (int kt = 0; kt <= qt; kt++) {
        const int k0 = kt * 64;
        __syncthreads();   // protect Kst/Vs/Ps reuse (also covers initial Q load)
#pragma unroll
        for (int it = 0; it < 8; it++) {
            int lin = tid + it * 256;
            int r = lin >> 5;
            int c4 = (lin & 31) * 4;
            float4 kv = *(const float4*)(kg + (size_t)(k0 + r) * 128 + c4);
            Kst[(c4 + 0) * 65 + r] = kv.x;
            Kst[(c4 + 1) * 65 + r] = kv.y;
            Kst[(c4 + 2) * 65 + r] = kv.z;
            Kst[(c4 + 3) * 65 + r] = kv.w;
            *(float4*)&Vs[r * 128 + c4] = *(const float4*)(vg + (size_t)(k0 + r) * 128 + c4);
        }
        __syncthreads();

        // Phase 1: S = scale * Q K^T (+ causal mask on diagonal tile)
        {
            float s[4][4];
#pragma unroll
            for (int i = 0; i < 4; i++)
#pragma unroll
                for (int j = 0; j < 4; j++) s[i][j] = 0.f;
#pragma unroll 4
            for (int k = 0; k < 128; k++) {
                float a[4], b[4];
#pragma unroll
                for (int i = 0; i < 4; i++) a[i] = Qs[(ty * 4 + i) * QS_STRIDE + k];
#pragma unroll
                for (int j = 0; j < 4; j++) b[j] = Kst[k * 65 + tx * 4 + j];
#pragma unroll
                for (int i = 0; i < 4; i++)
#pragma unroll
                    for (int j = 0; j < 4; j++) s[i][j] += a[i] * b[j];
            }
            const bool diag = (kt == qt);
#pragma unroll
            for (int i = 0; i < 4; i++) {
                int r = ty * 4 + i;
#pragma unroll
                for (int j = 0; j < 4; j++) {
                    int c = tx * 4 + j;
                    float v = s[i][j] * scale;
                    if (diag && c > r) v = -1e30f;
                    Ps[r * 65 + c] = v;
                }
            }
        }
        __syncthreads();

        // Phase 2: online softmax (4 lanes per row)
        {
            int row = tid >> 2;
            int l4 = tid & 3;
            float mx = -1e30f;
#pragma unroll
            for (int c = 0; c < 16; c++) mx = fmaxf(mx, Ps[row * 65 + l4 * 16 + c]);
            mx = fmaxf(mx, __shfl_xor_sync(0xffffffffu, mx, 1));
            mx = fmaxf(mx, __shfl_xor_sync(0xffffffffu, mx, 2));
            float m_old = m_s[row];
            float m_new = fmaxf(m_old, mx);
            float sum = 0.f;
#pragma unroll
            for (int c = 0; c < 16; c++) {
                float p = __expf(Ps[row * 65 + l4 * 16 + c] - m_new);
                Ps[row * 65 + l4 * 16 + c] = p;
                sum += p;
            }
            sum += __shfl_xor_sync(0xffffffffu, sum, 1);
            sum += __shfl_xor_sync(0xffffffffu, sum, 2);
            if (l4 == 0) {
                float alpha = __expf(m_old - m_new);   // first tile: exp(-inf)=0
                m_s[row] = m_new;
                l_s[row] = l_s[row] * alpha + sum;
                al_s[row] = alpha;
            }
        }
        __syncthreads();

        // Phase 3: acc = acc*alpha + P @ V
        {
#pragma unroll
            for (int i = 0; i < 4; i++) {
                float al = al_s[ty * 4 + i];
#pragma unroll
                for (int c = 0; c < 8; c++) acc[i][c] *= al;
            }
#pragma unroll 2
            for (int k = 0; k < 64; k++) {
                float p[4], v[8];
#pragma unroll
                for (int i = 0; i < 4; i++) p[i] = Ps[(ty * 4 + i) * 65 + k];
                *(float4*)(v)     = *(const float4*)&Vs[k * 128 + tx * 8];
                *(float4*)(v + 4) = *(const float4*)&Vs[k * 128 + tx * 8 + 4];
#pragma unroll
                for (int i = 0; i < 4; i++)
#pragma unroll
                    for (int c = 0; c < 8; c++) acc[i][c] += p[i] * v[c];
            }
        }
    }

    // Finalize: divide by l, write to g_att[B,T,C] (merge heads)
    {
        const int b_ = bh >> 4, h = bh & 15;
        float* outp = g_att + (size_t)b_ * TT * CC + (size_t)h * DD;
#pragma unroll
        for (int i = 0; i < 4; i++) {
            int r = ty * 4 + i;
            float inv = 1.f / l_s[r];
            float* o = outp + (size_t)(q0 + r) * CC + tx * 8;
            *(float4*)(o)     = make_float4(acc[i][0] * inv, acc[i][1] * inv,
                                            acc[i][2] * inv, acc[i][3] * inv);
            *(float4*)(o + 4) = make_float4(acc[i][4] * inv, acc[i][5] * inv,
                                            acc[i][6] * inv, acc[i][7] * inv);
        }
    }
}

// ---------------------------------------------------------------------------
// Output projection: out = g_att @ w_proj + b_proj  (double-buffered)
// ---------------------------------------------------------------------------
__global__ __launch_bounds__(256, 2) void proj_gemm_kernel(const float* __restrict__ W,
                                                           const float* __restrict__ bias,
                                                           float* __restrict__ out) {
    __shared__ float As[2][8][AS_STRIDE];
    __shared__ float Bs[2][8][128];

    const int bx = blockIdx.x;     // 0..15
    const int by = blockIdx.y;     // 0..63
    const int tid = threadIdx.x;
    const int tx = tid & 15, ty = tid >> 4;

    float acc[8][8];
#pragma unroll
    for (int i = 0; i < 8; i++)
#pragma unroll
        for (int j = 0; j < 8; j++) acc[i][j] = 0.f;

    const int ar = tid >> 1, ac = (tid & 1) * 4;
    const int br = tid >> 5, bc = (tid & 31) * 4;

    const float* Aptr = g_att + (size_t)(by * 128 + ar) * 2048 + ac;
    const float* Bptr = W + (size_t)br * 2048 + bx * 128 + bc;

    float4 av = *(const float4*)(Aptr);
    float4 bv = *(const float4*)(Bptr);
    As[0][ac + 0][ar] = av.x; As[0][ac + 1][ar] = av.y;
    As[0][ac + 2][ar] = av.z; As[0][ac + 3][ar] = av.w;
    *(float4*)&Bs[0][br][bc] = bv;
    __syncthreads();

    for (int k0 = 0; k0 < 2048; k0 += 8) {
        const int buf = (k0 >> 3) & 1;
        const int nxt = buf ^ 1;
        const bool more = (k0 + 8) < 2048;
        if (more) {
            av = *(const float4*)(Aptr + k0 + 8);
            bv = *(const float4*)(Bptr + (size_t)(k0 + 8) * 2048);
        }
#pragma unroll
        for (int kk = 0; kk < 8; kk++) {
            float a[8], b[8];
            *(float4*)(a)     = *(const float4*)&As[buf][kk][ty * 8];
            *(float4*)(a + 4) = *(const float4*)&As[buf][kk][ty * 8 + 4];
            *(float4*)(b)     = *(const float4*)&Bs[buf][kk][tx * 8];
            *(float4*)(b + 4) = *(const float4*)&Bs[buf][kk][tx * 8 + 4];
#pragma unroll
            for (int i = 0; i < 8; i++)
#pragma unroll
                for (int j = 0; j < 8; j++) acc[i][j] += a[i] * b[j];
        }
        if (more) {
            As[nxt][ac + 0][ar] = av.x; As[nxt][ac + 1][ar] = av.y;
            As[nxt][ac + 2][ar] = av.z; As[nxt][ac + 3][ar] = av.w;
            *(float4*)&Bs[nxt][br][bc] = bv;
        }
        __syncthreads();
    }

    const int n0 = bx * 128 + tx * 8;
    float bv0 = bias[n0 + 0], bv1 = bias[n0 + 1], bv2 = bias[n0 + 2], bv3 = bias[n0 + 3];
    float bv4 = bias[n0 + 4], bv5 = bias[n0 + 5], bv6 = bias[n0 + 6], bv7 = bias[n0 + 7];
#pragma unroll
    for (int i = 0; i < 8; i++) {
        int m = by * 128 + ty * 8 + i;
        float* o = out + (size_t)m * 2048 + n0;
        *(float4*)(o)     = make_float4(acc[i][0] + bv0, acc[i][1] + bv1,
                                        acc[i][2] + bv2, acc[i][3] + bv3);
        *(float4*)(o + 4) = make_float4(acc[i][4] + bv4, acc[i][5] + bv5,
                                        acc[i][6] + bv6, acc[i][7] + bv7);
    }
}

// ---------------------------------------------------------------------------
extern "C" void kernel_launch(void* const* d_in, const int* in_sizes, int n_in,
                              void* d_out, int out_size) {
    const float* x      = (const float*)d_in[0];
    const float* w_qkv  = (const float*)d_in[1];
    const float* w_proj = (const float*)d_in[2];
    const float* b_proj = (const float*)d_in[3];
    float* out = (float*)d_out;

    rope_table_kernel<<<TT, 64>>>();
    qkv_gemm_kernel<<<dim3(48, 64), 256>>>(x, w_qkv);
    cudaFuncSetAttribute(attn_kernel, cudaFuncAttributeMaxDynamicSharedMemorySize,
                         ATTN_SMEM_BYTES);
    attn_kernel<<<dim3(32, 64), 256, ATTN_SMEM_BYTES>>>();
    proj_gemm_kernel<<<dim3(16, 64), 256>>>(w_proj, b_proj, out);
}

// round 6
// speedup vs baseline: 1.3598x; 1.3598x over previous
#include <cuda_runtime.h>
#include <cuda_bf16.h>
#include <math.h>

// Problem constants
#define BB 4
#define TT 2048
#define CC 2048
#define HH 16
#define DD 128
#define N3 6144   // 3*C
#define MM 8192   // B*T
#define K3 6144   // split-K: 3*2048

// fp32 scratch
__device__ float g_q[BB*HH*TT*DD];     // [B,H,T,D]
__device__ float g_k[BB*HH*TT*DD];
__device__ float g_v[BB*HH*TT*DD];
__device__ float g_cos[TT*64];
__device__ float g_sin[TT*64];

// bf16 scratch (declared as uint4 for 16B alignment)
__device__ uint4 g_xa_raw[(size_t)MM*4096*2/16];      // x split [hi|lo]  [8192][4096]
__device__ uint4 g_aa_raw[(size_t)MM*4096*2/16];      // att split       [8192][4096]
__device__ uint4 g_wqkvT_raw[(size_t)N3*K3*2/16];     // w_qkv split^T   [6144][6144]
__device__ uint4 g_wprojT_raw[(size_t)CC*K3*2/16];    // w_proj split^T  [2048][6144]
#define G_XA    ((__nv_bfloat16*)g_xa_raw)
#define G_AA    ((__nv_bfloat16*)g_aa_raw)
#define G_WQKVT ((__nv_bfloat16*)g_wqkvT_raw)
#define G_WPROJT ((__nv_bfloat16*)g_wprojT_raw)

// ---------------------------------------------------------------------------
__global__ void rope_table_kernel() {
    int t = blockIdx.x;
    int j = threadIdx.x;            // 0..63
    float inv = (float)(1.0 / pow(10000.0, (2.0 * j) / 128.0));
    float s, c;
    sincosf((float)t * inv, &s, &c);
    g_cos[t * 64 + j] = c;
    g_sin[t * 64 + j] = s;
}

// ---------------------------------------------------------------------------
__device__ __forceinline__ void split2(float v, __nv_bfloat16& h, __nv_bfloat16& l) {
    h = __float2bfloat16(v);
    l = __float2bfloat16(v - __bfloat162float(h));
}

// x [M][2048] f32 -> G_XA [M][4096] bf16 as [hi | lo]
__global__ __launch_bounds__(256) void split_x_kernel(const float* __restrict__ in) {
    int idx = blockIdx.x * 256 + threadIdx.x;       // over M*2048/4
    int m = idx >> 9;                                // 512 float4 per row
    int kc = (idx & 511) * 4;
    float4 v = *(const float4*)(in + (size_t)m * 2048 + kc);
    __nv_bfloat16 h[4], l[4];
    split2(v.x, h[0], l[0]); split2(v.y, h[1], l[1]);
    split2(v.z, h[2], l[2]); split2(v.w, h[3], l[3]);
    __nv_bfloat16* oh = G_XA + (size_t)m * 4096 + kc;
    *(__nv_bfloat162*)(oh)     = __nv_bfloat162{h[0], h[1]};
    *(__nv_bfloat162*)(oh + 2) = __nv_bfloat162{h[2], h[3]};
    __nv_bfloat16* ol = oh + 2048;
    *(__nv_bfloat162*)(ol)     = __nv_bfloat162{l[0], l[1]};
    *(__nv_bfloat162*)(ol + 2) = __nv_bfloat162{l[2], l[3]};
}

// W [2048][N] f32 -> BT [N][6144] bf16 as rows n: [hi(k) | lo(k) | hi(k)]
__global__ __launch_bounds__(256) void wsplitT_kernel(const float* __restrict__ W,
                                                      int N, int which) {
    __shared__ float s[32][33];
    __nv_bfloat16* BT = which ? G_WPROJT : G_WQKVT;
    const int n0 = blockIdx.x * 32;
    const int k0 = blockIdx.y * 32;
    const int tx = threadIdx.x & 31, ty8 = threadIdx.x >> 5;
#pragma unroll
    for (int i = ty8; i < 32; i += 8)
        s[i][tx] = W[(size_t)(k0 + i) * N + n0 + tx];
    __syncthreads();
#pragma unroll
    for (int i = ty8; i < 32; i += 8) {
        float v = s[tx][i];                       // W[k0+tx][n0+i]
        __nv_bfloat16 h, l; split2(v, h, l);
        __nv_bfloat16* row = BT + (size_t)(n0 + i) * K3;
        row[k0 + tx]        = h;
        row[2048 + k0 + tx] = l;
        row[4096 + k0 + tx] = h;
    }
}

// ---------------------------------------------------------------------------
// bf16 MMA helper
// ---------------------------------------------------------------------------
__device__ __forceinline__ void mma16816(float* c, unsigned a0, unsigned a1,
                                         unsigned a2, unsigned a3,
                                         unsigned b0, unsigned b1) {
    asm volatile(
        "mma.sync.aligned.m16n8k16.row.col.f32.bf16.bf16.f32 "
        "{%0,%1,%2,%3}, {%4,%5,%6,%7}, {%8,%9}, {%0,%1,%2,%3};\n"
        : "+f"(c[0]), "+f"(c[1]), "+f"(c[2]), "+f"(c[3])
        : "r"(a0), "r"(a1), "r"(a2), "r"(a3), "r"(b0), "r"(b1));
}

#define LDT 40            // smem tile stride in bf16 (conflict-free frag reads)
#define TILE_ELEMS (128*LDT)
#define NKT 192           // 6144/32 k-tiles

// ---------------------------------------------------------------------------
// QKV mma GEMM: [8192 x 6144] = A'(split x) @ B'(split w_qkv), fused RoPE.
// Block 128x128x32, 8 warps of 32x64. Epilogue via smem (RoPE pairs cross warps).
// ---------------------------------------------------------------------------
#define QKV_SMEM_BYTES (128*132*4)   // epi buffer (67584) > tiles (40960)

__global__ __launch_bounds__(256) void qkv_mma_kernel() {
    extern __shared__ __align__(16) unsigned char smraw[];
    __nv_bfloat16* As = (__nv_bfloat16*)smraw;            // [2][128][40]
    __nv_bfloat16* Bs = As + 2 * TILE_ELEMS;              // [2][128][40]
    float* epi = (float*)smraw;                           // [128][132]

    const int t = threadIdx.x;
    const int bn = blockIdx.x, bm = blockIdx.y;
    const int wid = t >> 5, lane = t & 31;
    const int wm = wid >> 1, wn = wid & 1;
    const int gid = lane >> 2, tig = lane & 3;

    const int r0 = t >> 2, cc = t & 3;                    // load chunks
    const __nv_bfloat16* pA0 = G_XA + (size_t)(bm * 128 + r0) * 4096 + cc * 8;
    const __nv_bfloat16* pA1 = pA0 + (size_t)64 * 4096;
    const __nv_bfloat16* pB0 = G_WQKVT + (size_t)(bn * 128 + r0) * K3 + cc * 8;
    const __nv_bfloat16* pB1 = pB0 + (size_t)64 * K3;
    __nv_bfloat16* sA0 = As + r0 * LDT + cc * 8;
    __nv_bfloat16* sA1 = sA0 + 64 * LDT;
    __nv_bfloat16* sB0 = Bs + r0 * LDT + cc * 8;
    __nv_bfloat16* sB1 = sB0 + 64 * LDT;

    float acc[2][8][4];
#pragma unroll
    for (int mt = 0; mt < 2; mt++)
#pragma unroll
        for (int nt = 0; nt < 8; nt++)
#pragma unroll
            for (int i = 0; i < 4; i++) acc[mt][nt][i] = 0.f;

    // preload tile 0
    {
        *(uint4*)sA0 = *(const uint4*)(pA0 + 0);
        *(uint4*)sA1 = *(const uint4*)(pA1 + 0);
        *(uint4*)sB0 = *(const uint4*)(pB0 + 0);
        *(uint4*)sB1 = *(const uint4*)(pB1 + 0);
    }
    __syncthreads();

    for (int kt = 0; kt < NKT; kt++) {
        const int buf = kt & 1;
        const bool more = (kt + 1) < NKT;
        uint4 ra0, ra1, rb0, rb1;
        if (more) {
            const int ktn = kt + 1;
            const int kA = (ktn < 64) ? ktn * 32 : (ktn - 64) * 32;
            const int kB = ktn * 32;
            ra0 = *(const uint4*)(pA0 + kA);
            ra1 = *(const uint4*)(pA1 + kA);
            rb0 = *(const uint4*)(pB0 + kB);
            rb1 = *(const uint4*)(pB1 + kB);
        }
        const __nv_bfloat16* Asb = As + buf * TILE_ELEMS;
        const __nv_bfloat16* Bsb = Bs + buf * TILE_ELEMS;
#pragma unroll
        for (int ks = 0; ks < 2; ks++) {
            const int k16 = ks * 16;
            unsigned a[2][4];
#pragma unroll
            for (int mt = 0; mt < 2; mt++) {
                const __nv_bfloat16* ap = Asb + (wm * 32 + mt * 16 + gid) * LDT + k16 + tig * 2;
                a[mt][0] = *(const unsigned*)(ap);
                a[mt][1] = *(const unsigned*)(ap + 8 * LDT);
                a[mt][2] = *(const unsigned*)(ap + 8);
                a[mt][3] = *(const unsigned*)(ap + 8 * LDT + 8);
            }
#pragma unroll
            for (int nt = 0; nt < 8; nt++) {
                const __nv_bfloat16* bp = Bsb + (wn * 64 + nt * 8 + gid) * LDT + k16 + tig * 2;
                unsigned b0 = *(const unsigned*)(bp);
                unsigned b1 = *(const unsigned*)(bp + 8);
                mma16816(acc[0][nt], a[0][0], a[0][1], a[0][2], a[0][3], b0, b1);
                mma16816(acc[1][nt], a[1][0], a[1][1], a[1][2], a[1][3], b0, b1);
            }
        }
        if (more) {
            const int nb = buf ^ 1;
            *(uint4*)(sA0 + nb * TILE_ELEMS) = ra0;
            *(uint4*)(sA1 + nb * TILE_ELEMS) = ra1;
            *(uint4*)(sB0 + nb * TILE_ELEMS) = rb0;
            *(uint4*)(sB1 + nb * TILE_ELEMS) = rb1;
        }
        __syncthreads();
    }

    // dump acc -> epi smem
#pragma unroll
    for (int mt = 0; mt < 2; mt++)
#pragma unroll
        for (int nt = 0; nt < 8; nt++) {
            int row = wm * 32 + mt * 16 + gid;
            int col = wn * 64 + nt * 8 + tig * 2;
            epi[row * 132 + col]           = acc[mt][nt][0];
            epi[row * 132 + col + 1]       = acc[mt][nt][1];
            epi[(row + 8) * 132 + col]     = acc[mt][nt][2];
            epi[(row + 8) * 132 + col + 1] = acc[mt][nt][3];
        }
    __syncthreads();

    // RoPE (q,k) + scatter to [B,H,T,D]
    const int n0 = bn * 128;
    const int which = n0 >> 11;
    const int h = (n0 & 2047) >> 7;
    const int b_ = bm >> 4;
    const int t0 = (bm & 15) * 128;
    float* base = (which == 0) ? g_q : ((which == 1) ? g_k : g_v);
    const int r = t >> 1, half = t & 1;
    const int tglob = t0 + r;
    float* orow = base + (size_t)(b_ * HH + h) * TT * DD + (size_t)tglob * DD;

    if (which < 2) {
        const float* crow = g_cos + tglob * 64 + half * 32;
        const float* srow = g_sin + tglob * 64 + half * 32;
#pragma unroll
        for (int j4 = 0; j4 < 8; j4++) {
            int j = half * 32 + j4 * 4;
            float4 x1 = *(float4*)&epi[r * 132 + j];
            float4 x2 = *(float4*)&epi[r * 132 + j + 64];
            float4 c4 = *(const float4*)(crow + j4 * 4);
            float4 s4 = *(const float4*)(srow + j4 * 4);
            float4 o1, o2;
            o1.x = x1.x * c4.x - x2.x * s4.x;  o2.x = x2.x * c4.x + x1.x * s4.x;
            o1.y = x1.y * c4.y - x2.y * s4.y;  o2.y = x2.y * c4.y + x1.y * s4.y;
            o1.z = x1.z * c4.z - x2.z * s4.z;  o2.z = x2.z * c4.z + x1.z * s4.z;
            o1.w = x1.w * c4.w - x2.w * s4.w;  o2.w = x2.w * c4.w + x1.w * s4.w;
            *(float4*)&orow[j]      = o1;
            *(float4*)&orow[j + 64] = o2;
        }
    } else {
#pragma unroll
        for (int j4 = 0; j4 < 16; j4++) {
            int j = half * 64 + j4 * 4;
            *(float4*)&orow[j] = *(float4*)&epi[r * 132 + j];
        }
    }
}

// ---------------------------------------------------------------------------
// Proj mma GEMM: out[8192x2048] = A'(split att) @ B'(split w_proj) + bias
// ---------------------------------------------------------------------------
#define PROJ_SMEM_BYTES (4*TILE_ELEMS*2)   // 40960

__global__ __launch_bounds__(256) void proj_mma_kernel(const float* __restrict__ bias,
                                                       float* __restrict__ out) {
    extern __shared__ __align__(16) unsigned char smraw[];
    __nv_bfloat16* As = (__nv_bfloat16*)smraw;
    __nv_bfloat16* Bs = As + 2 * TILE_ELEMS;

    const int t = threadIdx.x;
    const int bn = blockIdx.x, bm = blockIdx.y;
    const int wid = t >> 5, lane = t & 31;
    const int wm = wid >> 1, wn = wid & 1;
    const int gid = lane >> 2, tig = lane & 3;

    const int r0 = t >> 2, cc = t & 3;
    const __nv_bfloat16* pA0 = G_AA + (size_t)(bm * 128 + r0) * 4096 + cc * 8;
    const __nv_bfloat16* pA1 = pA0 + (size_t)64 * 4096;
    const __nv_bfloat16* pB0 = G_WPROJT + (size_t)(bn * 128 + r0) * K3 + cc * 8;
    const __nv_bfloat16* pB1 = pB0 + (size_t)64 * K3;
    __nv_bfloat16* sA0 = As + r0 * LDT + cc * 8;
    __nv_bfloat16* sA1 = sA0 + 64 * LDT;
    __nv_bfloat16* sB0 = Bs + r0 * LDT + cc * 8;
    __nv_bfloat16* sB1 = sB0 + 64 * LDT;

    float acc[2][8][4];
#pragma unroll
    for (int mt = 0; mt < 2; mt++)
#pragma unroll
        for (int nt = 0; nt < 8; nt++)
#pragma unroll
            for (int i = 0; i < 4; i++) acc[mt][nt][i] = 0.f;

    {
        *(uint4*)sA0 = *(const uint4*)(pA0 + 0);
        *(uint4*)sA1 = *(const uint4*)(pA1 + 0);
        *(uint4*)sB0 = *(const uint4*)(pB0 + 0);
        *(uint4*)sB1 = *(const uint4*)(pB1 + 0);
    }
    __syncthreads();

    for (int kt = 0; kt < NKT; kt++) {
        const int buf = kt & 1;
        const bool more = (kt + 1) < NKT;
        uint4 ra0, ra1, rb0, rb1;
        if (more) {
            const int ktn = kt + 1;
            const int kA = (ktn < 64) ? ktn * 32 : (ktn - 64) * 32;
            const int kB = ktn * 32;
            ra0 = *(const uint4*)(pA0 + kA);
            ra1 = *(const uint4*)(pA1 + kA);
            rb0 = *(const uint4*)(pB0 + kB);
            rb1 = *(const uint4*)(pB1 + kB);
        }
        const __nv_bfloat16* Asb = As + buf * TILE_ELEMS;
        const __nv_bfloat16* Bsb = Bs + buf * TILE_ELEMS;
#pragma unroll
        for (int ks = 0; ks < 2; ks++) {
            const int k16 = ks * 16;
            unsigned a[2][4];
#pragma unroll
            for (int mt = 0; mt < 2; mt++) {
                const __nv_bfloat16* ap = Asb + (wm * 32 + mt * 16 + gid) * LDT + k16 + tig * 2;
                a[mt][0] = *(const unsigned*)(ap);
                a[mt][1] = *(const unsigned*)(ap + 8 * LDT);
                a[mt][2] = *(const unsigned*)(ap + 8);
                a[mt][3] = *(const unsigned*)(ap + 8 * LDT + 8);
            }
#pragma unroll
            for (int nt = 0; nt < 8; nt++) {
                const __nv_bfloat16* bp = Bsb + (wn * 64 + nt * 8 + gid) * LDT + k16 + tig * 2;
                unsigned b0 = *(const unsigned*)(bp);
                unsigned b1 = *(const unsigned*)(bp + 8);
                mma16816(acc[0][nt], a[0][0], a[0][1], a[0][2], a[0][3], b0, b1);
                mma16816(acc[1][nt], a[1][0], a[1][1], a[1][2], a[1][3], b0, b1);
            }
        }
        if (more) {
            const int nb = buf ^ 1;
            *(uint4*)(sA0 + nb * TILE_ELEMS) = ra0;
            *(uint4*)(sA1 + nb * TILE_ELEMS) = ra1;
            *(uint4*)(sB0 + nb * TILE_ELEMS) = rb0;
            *(uint4*)(sB1 + nb * TILE_ELEMS) = rb1;
        }
        __syncthreads();
    }

    // epilogue: bias + store
#pragma unroll
    for (int mt = 0; mt < 2; mt++)
#pragma unroll
        for (int nt = 0; nt < 8; nt++) {
            int row = bm * 128 + wm * 32 + mt * 16 + gid;
            int col = bn * 128 + wn * 64 + nt * 8 + tig * 2;
            float b0 = bias[col], b1 = bias[col + 1];
            *(float2*)&out[(size_t)row * 2048 + col] =
                make_float2(acc[mt][nt][0] + b0, acc[mt][nt][1] + b1);
            *(float2*)&out[(size_t)(row + 8) * 2048 + col] =
                make_float2(acc[mt][nt][2] + b0, acc[mt][nt][3] + b1);
        }
}

// ---------------------------------------------------------------------------
// Causal flash attention (fp32). Epilogue now writes bf16 hi/lo straight into
// G_AA (the proj GEMM input), eliminating the separate split_att pass.
// ---------------------------------------------------------------------------
#define QS_STRIDE 132
#define ATTN_SMEM_FLOATS (64*QS_STRIDE + 128*65 + 64*128 + 64*65 + 192)
#define ATTN_SMEM_BYTES  (ATTN_SMEM_FLOATS * 4)

__global__ __launch_bounds__(256) void attn_kernel() {
    extern __shared__ float sm[];
    float* Qs  = sm;
    float* Kst = Qs + 64 * QS_STRIDE;
    float* Vs  = Kst + 128 * 65;
    float* Ps  = Vs + 64 * 128;
    float* m_s  = Ps + 64 * 65;
    float* l_s  = m_s + 64;
    float* al_s = l_s + 64;

    const int tid = threadIdx.x;
    const int tx = tid & 15, ty = tid >> 4;
    const int bh = blockIdx.y;
    const int qt = blockIdx.x;
    const int q0 = qt * 64;
    const float scale = 0.08838834764831845f;

    const float* qg = g_q + (size_t)bh * TT * DD;
    const float* kg = g_k + (size_t)bh * TT * DD;
    const float* vg = g_v + (size_t)bh * TT * DD;

#pragma unroll
    for (int it = 0; it < 8; it++) {
        int lin = tid + it * 256;
        int r = lin >> 5;
        int c4 = (lin & 31) * 4;
        *(float4*)&Qs[r * QS_STRIDE + c4] = *(const float4*)(qg + (size_t)(q0 + r) * 128 + c4);
    }
    if (tid < 64) { m_s[tid] = -INFINITY; l_s[tid] = 0.f; }

    float acc[4][8];
#pragma unroll
    for (int i = 0; i < 4; i++)
#pragma unroll
        for (int c = 0; c < 8; c++) acc[i][c] = 0.f;

    for (int kt = 0; kt <= qt; kt++) {
        const int k0 = kt * 64;
        __syncthreads();
#pragma unroll
        for (int it = 0; it < 8; it++) {
            int lin = tid + it * 256;
            int r = lin >> 5;
            int c4 = (lin & 31) * 4;
            float4 kv = *(const float4*)(kg + (size_t)(k0 + r) * 128 + c4);
            Kst[(c4 + 0) * 65 + r] = kv.x;
            Kst[(c4 + 1) * 65 + r] = kv.y;
            Kst[(c4 + 2) * 65 + r] = kv.z;
            Kst[(c4 + 3) * 65 + r] = kv.w;
            *(float4*)&Vs[r * 128 + c4] = *(const float4*)(vg + (size_t)(k0 + r) * 128 + c4);
        }
        __syncthreads();

        {
            float s[4][4];
#pragma unroll
            for (int i = 0; i < 4; i++)
#pragma unroll
                for (int j = 0; j < 4; j++) s[i][j] = 0.f;
#pragma unroll 4
            for (int k = 0; k < 128; k++) {
                float a[4], b[4];
#pragma unroll
                for (int i = 0; i < 4; i++) a[i] = Qs[(ty * 4 + i) * QS_STRIDE + k];
#pragma unroll
                for (int j = 0; j < 4; j++) b[j] = Kst[k * 65 + tx * 4 + j];
#pragma unroll
                for (int i = 0; i < 4; i++)
#pragma unroll
                    for (int j = 0; j < 4; j++) s[i][j] += a[i] * b[j];
            }
            const bool diag = (kt == qt);
#pragma unroll
            for (int i = 0; i < 4; i++) {
                int r = ty * 4 + i;
#pragma unroll
                for (int j = 0; j < 4; j++) {
                    int c = tx * 4 + j;
                    float v = s[i][j] * scale;
                    if (diag && c > r) v = -1e30f;
                    Ps[r * 65 + c] = v;
                }
            }
        }
        __syncthreads();

        {
            int row = tid >> 2;
            int l4 = tid & 3;
            float mx = -1e30f;
#pragma unroll
            for (int c = 0; c < 16; c++) mx = fmaxf(mx, Ps[row * 65 + l4 * 16 + c]);
            mx = fmaxf(mx, __shfl_xor_sync(0xffffffffu, mx, 1));
            mx = fmaxf(mx, __shfl_xor_sync(0xffffffffu, mx, 2));
            float m_old = m_s[row];
            float m_new = fmaxf(m_old, mx);
            float sum = 0.f;
#pragma unroll
            for (int c = 0; c < 16; c++) {
                float p = __expf(Ps[row * 65 + l4 * 16 + c] - m_new);
                Ps[row * 65 + l4 * 16 + c] = p;
                sum += p;
            }
            sum += __shfl_xor_sync(0xffffffffu, sum, 1);
            sum += __shfl_xor_sync(0xffffffffu, sum, 2);
            if (l4 == 0) {
                float alpha = __expf(m_old - m_new);
                m_s[row] = m_new;
                l_s[row] = l_s[row] * alpha + sum;
                al_s[row] = alpha;
            }
        }
        __syncthreads();

        {
#pragma unroll
            for (int i = 0; i < 4; i++) {
                float al = al_s[ty * 4 + i];
#pragma unroll
                for (int c = 0; c < 8; c++) acc[i][c] *= al;
            }
#pragma unroll 2
            for (int k = 0; k < 64; k++) {
                float p[4], v[8];
#pragma unroll
                for (int i = 0; i < 4; i++) p[i] = Ps[(ty * 4 + i) * 65 + k];
                *(float4*)(v)     = *(const float4*)&Vs[k * 128 + tx * 8];
                *(float4*)(v + 4) = *(const float4*)&Vs[k * 128 + tx * 8 + 4];
#pragma unroll
                for (int i = 0; i < 4; i++)
#pragma unroll
                    for (int c = 0; c < 8; c++) acc[i][c] += p[i] * v[c];
            }
        }
    }

    // Finalize: divide by l, split hi/lo, write straight into G_AA [8192][4096].
    // G_AA row = b*2048 + t, hi at col h*128+d, lo at col 2048 + h*128 + d.
    {
        const int b_ = bh >> 4, h = bh & 15;
#pragma unroll
        for (int i = 0; i < 4; i++) {
            int r = ty * 4 + i;
            float inv = 1.f / l_s[r];
            __nv_bfloat16 hh[8], ll[8];
#pragma unroll
            for (int c = 0; c < 8; c++) split2(acc[i][c] * inv, hh[c], ll[c]);
            __nv_bfloat16* rowp = G_AA + (size_t)(b_ * TT + q0 + r) * 4096 + h * DD + tx * 8;
            *(uint4*)(rowp)        = *(uint4*)hh;
            *(uint4*)(rowp + 2048) = *(uint4*)ll;
        }
    }
}

// ---------------------------------------------------------------------------
extern "C" void kernel_launch(void* const* d_in, const int* in_sizes, int n_in,
                              void* d_out, int out_size) {
    const float* x      = (const float*)d_in[0];
    const float* w_qkv  = (const float*)d_in[1];
    const float* w_proj = (const float*)d_in[2];
    const float* b_proj = (const float*)d_in[3];
    float* out = (float*)d_out;

    cudaFuncSetAttribute(attn_kernel, cudaFuncAttributeMaxDynamicSharedMemorySize,
                         ATTN_SMEM_BYTES);
    cudaFuncSetAttribute(qkv_mma_kernel, cudaFuncAttributeMaxDynamicSharedMemorySize,
                         QKV_SMEM_BYTES);
    cudaFuncSetAttribute(proj_mma_kernel, cudaFuncAttributeMaxDynamicSharedMemorySize,
                         PROJ_SMEM_BYTES);

    rope_table_kernel<<<TT, 64>>>();
    split_x_kernel<<<MM * 2048 / 4 / 256, 256>>>(x);
    wsplitT_kernel<<<dim3(N3 / 32, 2048 / 32), 256>>>(w_qkv, N3, 0);
    qkv_mma_kernel<<<dim3(48, 64), 256, QKV_SMEM_BYTES>>>();
    attn_kernel<<<dim3(32, 64), 256, ATTN_SMEM_BYTES>>>();
    wsplitT_kernel<<<dim3(CC / 32, 2048 / 32), 256>>>(w_proj, CC, 1);
    proj_mma_kernel<<<dim3(16, 64), 256, PROJ_SMEM_BYTES>>>(b_proj, out);
}